// round 8
// baseline (speedup 1.0000x reference)
#include <cuda_runtime.h>
#include <cuda_fp16.h>
#include <stdint.h>

#define NB 8      // batch
#define TT 8      // time (slice t = TT/2)
#define V  512    // nodes
#define F  64     // features
#define KP 32     // feature pairs (F/2)
#define JT 32     // j-columns per CTA
#define TPB 512   // 16 warps
#define YSTRIDE 72  // yrow stride in halfs (144B -> conflict-free LDS.128 in transpose)

// smem byte offsets
#define Y2_BYTES   (KP * V * 4)            // 65536: y2[k][v] half2
#define YROW_BYTES (V * YSTRIDE * 2)       // 73728
#define OFF_Y2     0
#define OFF_YROW   Y2_BYTES
#define OFF_PART   (OFF_YROW + YROW_BYTES) // partial[8][32] f32
#define OFF_CINV   (OFF_PART + 8 * 32 * 4) // colinv[32] f32
#define OFF_SA2    (OFF_CINV + 32 * 4)     // sa2[32] half2
#define SMEM_TOTAL (OFF_SA2 + 32 * 4)

// One CTA per (n, 32-col j-tile). GEMM-style tiling: warp = 64i x 16j (two
// 32x16 tiles), thread = 4i x 4j. Feature-major fp16 layout => each LDS.128
// feeds 16 independent fma-pipe chains (no broadcast waste): crossbar floor
// ~8.5K cyc/SM < fma floor 16.4K cyc/SM.
__global__ __launch_bounds__(TPB, 1)
void graph_learn_kernel(const float* __restrict__ x,
                        const float* __restrict__ a,
                        float* __restrict__ out) {
    extern __shared__ char sm[];
    uint32_t* y2u   = (uint32_t*)(sm + OFF_Y2);    // [KP][512] half2-as-u32
    __half*   yrow  = (__half*)(sm + OFF_YROW);    // [V][YSTRIDE]
    float*  partial = (float*)(sm + OFF_PART);     // [8][32]
    float*  colinv  = (float*)(sm + OFF_CINV);     // [32]
    __half2* sa2    = (__half2*)(sm + OFF_SA2);    // [KP]

    const int n    = blockIdx.y;
    const int j0   = blockIdx.x * JT;
    const int tid  = threadIdx.x;
    const int lane = tid & 31;
    const int wid  = tid >> 5;
    const int r    = lane >> 2;   // 0..7  (i within warp)
    const int c    = lane & 3;    // 0..3  (j within warp)
    const int wr   = wid >> 1;    // 0..7  (warp i-row)
    const int wj   = wid & 1;     // 0..1  (warp j-half)

    // ---- stage xm[n] = x[n, TT/2, :, :] as fp16 into yrow (coalesced) ----
    const float4* xg = (const float4*)(x + ((size_t)n * TT + TT / 2) * V * F);
    for (int idx = tid; idx < V * F / 4; idx += TPB) {
        int v = idx >> 4, k = idx & 15;
        float4 w = xg[idx];
        *(__half2*)(yrow + v * YSTRIDE + k * 4)     = __float22half2_rn(make_float2(w.x, w.y));
        *(__half2*)(yrow + v * YSTRIDE + k * 4 + 2) = __float22half2_rn(make_float2(w.z, w.w));
    }
    if (tid < KP) sa2[tid] = __float22half2_rn(make_float2(a[2 * tid], a[2 * tid + 1]));
    __syncthreads();

    // ---- transpose yrow -> y2 (feature-major): 128 blocks of (4 fpairs x 32 v) ----
#pragma unroll
    for (int m = 0; m < 8; m++) {
        int b  = wid * 8 + m;
        int kc = b & 7;
        int v  = ((b >> 3) << 5) + lane;
        uint4 w = *(const uint4*)(yrow + v * YSTRIDE + kc * 8);
        y2u[(4 * kc + 0) * V + v] = w.x;
        y2u[(4 * kc + 1) * V + v] = w.y;
        y2u[(4 * kc + 2) * V + v] = w.z;
        y2u[(4 * kc + 3) * V + v] = w.w;
    }
    __syncthreads();

    const int jb   = wj * 16;                 // local j base within tile
    const int jcol = j0 + jb + 4 * c;         // GLOBAL j node base (R7 bugfix)
    float t[2][16];
    float cs[4] = {0.f, 0.f, 0.f, 0.f};

#pragma unroll 1
    for (int tile = 0; tile < 2; tile++) {
        const int tb = wr * 64 + tile * 32;   // i base; thread is = tb+4r..+3
        const __half2 z = __float2half2_rn(0.0f);
        __half2 acc0[16], acc1[16];
#pragma unroll
        for (int p = 0; p < 16; p++) { acc0[p] = z; acc1[p] = z; }

        // two 16-k banks: fp16 chains of length 16 each (precision), static
        // acc indexing (no dynamic register indexing -> no local spills)
#pragma unroll 1
        for (int bank = 0; bank < 2; bank++) {
            __half2* acc = bank ? acc1 : acc0;
#pragma unroll 4
            for (int k8 = 0; k8 < 16; k8++) {
                const int k = bank * 16 + k8;
                const uint32_t* prow = y2u + k * V;
                uint4 iw = *(const uint4*)(prow + tb + 4 * r);
                uint4 jw = *(const uint4*)(prow + jcol);
                __half2 ifr[4] = {*(__half2*)&iw.x, *(__half2*)&iw.y,
                                  *(__half2*)&iw.z, *(__half2*)&iw.w};
                __half2 jfr[4] = {*(__half2*)&jw.x, *(__half2*)&jw.y,
                                  *(__half2*)&jw.z, *(__half2*)&jw.w};
                __half2 ak = sa2[k];
#pragma unroll
                for (int ii = 0; ii < 4; ii++)
#pragma unroll
                    for (int jj = 0; jj < 4; jj++) {
                        __half2 d = __habs2(__hsub2(ifr[ii], jfr[jj]));
                        acc[ii * 4 + jj] = __hfma2(d, ak, acc[ii * 4 + jj]);
                    }
            }
        }

        // epilogue: combine banks in f32, 16 independent exp chains
#pragma unroll
        for (int p = 0; p < 16; p++) {
            float2 f = __half22float2(acc0[p]);
            float2 g = __half22float2(acc1[p]);
            float s  = (f.x + f.y) + (g.x + g.y);
            t[tile][p] = __expf(fmaxf(s, 0.0f));
        }
#pragma unroll
        for (int jj = 0; jj < 4; jj++)
            cs[jj] += (t[tile][0 * 4 + jj] + t[tile][1 * 4 + jj])
                    + (t[tile][2 * 4 + jj] + t[tile][3 * 4 + jj]);
    }

    // ---- reduce column sums over r (lanes differing in bits 2..4) ----
#pragma unroll
    for (int m = 4; m <= 16; m <<= 1)
#pragma unroll
        for (int jj = 0; jj < 4; jj++)
            cs[jj] += __shfl_xor_sync(0xFFFFFFFFu, cs[jj], m);
    if (r == 0) {
#pragma unroll
        for (int jj = 0; jj < 4; jj++)
            partial[wr * 32 + jb + 4 * c + jj] = cs[jj];
    }
    __syncthreads();
    if (tid < 32) {
        float s = 0.0f;
#pragma unroll
        for (int w = 0; w < 8; w++) s += partial[w * 32 + tid];
        colinv[tid] = 1.0f / s;
    }
    __syncthreads();

    // ---- normalize + store: thread's 4 j consecutive -> float4 STG ----
    float4 inv4 = *(const float4*)(colinv + jb + 4 * c);
    float* obase = out + (size_t)n * V * V + jcol;
#pragma unroll
    for (int tile = 0; tile < 2; tile++)
#pragma unroll
        for (int ii = 0; ii < 4; ii++) {
            int i = wr * 64 + tile * 32 + 4 * r + ii;
            float4 o;
            o.x = t[tile][ii * 4 + 0] * inv4.x;
            o.y = t[tile][ii * 4 + 1] * inv4.y;
            o.z = t[tile][ii * 4 + 2] * inv4.z;
            o.w = t[tile][ii * 4 + 3] * inv4.w;
            *(float4*)(obase + (size_t)i * V) = o;
        }
}

extern "C" void kernel_launch(void* const* d_in, const int* in_sizes, int n_in,
                              void* d_out, int out_size) {
    const float* x = (const float*)d_in[0];
    const float* a = (const float*)d_in[1];
    if (n_in >= 2 && in_sizes[0] == F && in_sizes[1] == NB * TT * V * F) {
        const float* t = x; x = a; a = t;
    }
    float* out = (float*)d_out;

    cudaFuncSetAttribute(graph_learn_kernel,
                         cudaFuncAttributeMaxDynamicSharedMemorySize, SMEM_TOTAL);
    dim3 grid(V / JT, NB);
    graph_learn_kernel<<<grid, TPB, SMEM_TOTAL>>>(x, a, out);
}

// round 9
// speedup vs baseline: 1.2939x; 1.2939x over previous
#include <cuda_runtime.h>
#include <cuda_fp16.h>
#include <stdint.h>

#define NB 8      // batch
#define TT 8      // time (slice t = TT/2)
#define V  512    // nodes
#define F  64     // features
#define KP 32     // feature pairs
#define BLK 64    // tile edge
#define NBLK 8    // V/BLK
#define NPAIR 36  // NBLK*(NBLK+1)/2
#define TPB 256   // 8 warps: 2x4 warp grid, warp tile 32i x 16j, thread 4x4

// colpartial[n][row-block b][column j] = sum_{i in block b} tmpS[i][j].
// Each entry written by exactly one CTA (pair (min,max)) -> no atomics.
__device__ float g_colpartial[NB][NBLK][V];

// ---------------- Kernel 1: symmetric tile compute ----------------
__global__ __launch_bounds__(TPB)
void tile_kernel(const float* __restrict__ x,
                 const float* __restrict__ a,
                 float* __restrict__ out) {
    __shared__ __half    yrow[2 * BLK][72];   // staging, row-major (144B rows)
    __shared__ uint32_t  y2[KP][2 * BLK];     // feature-major half2: [k][v], v<64 = i-block, v>=64 = j-block
    __shared__ float     cpart[2][BLK];       // per-wy column partials
    __shared__ float     rpart[4][BLK];       // per-wx row partials
    __shared__ __half2   sa2[KP];

    const int n   = blockIdx.y;
    int p = 0, rem = blockIdx.x;              // decode pair (p <= q)
    while (rem > (NBLK - 1) - p) { rem -= NBLK - p; p++; }
    const int q = p + rem;

    const int tid  = threadIdx.x;
    const int lane = tid & 31, wid = tid >> 5;
    const int r    = lane >> 2, c = lane & 3; // thread 4i x 4j within warp
    const int wy   = wid >> 2,  wx = wid & 3; // warp 32i x 16j within tile

    // ---- load i-block (rows 64p..) and j-block (rows 64q..) as fp16 ----
    const float4* xg = (const float4*)(x + ((size_t)n * TT + TT / 2) * V * F);
    for (int it = 0; it < 8; it++) {
        int idx = it * TPB + tid;
        int v = idx >> 4, ch = idx & 15;
        int src = (v < BLK) ? (BLK * p + v) : (BLK * q + (v - BLK));
        float4 w = xg[(size_t)src * 16 + ch];
        *(__half2*)&yrow[v][ch * 4]     = __float22half2_rn(make_float2(w.x, w.y));
        *(__half2*)&yrow[v][ch * 4 + 2] = __float22half2_rn(make_float2(w.z, w.w));
    }
    if (tid < KP) sa2[tid] = __float22half2_rn(make_float2(a[2 * tid], a[2 * tid + 1]));
    __syncthreads();

    // ---- transpose to feature-major: 32 units of (4 fpairs x 32 v) ----
#pragma unroll
    for (int m = 0; m < 4; m++) {
        int u  = wid * 4 + m;
        int kc = u >> 2, vg = u & 3;
        int v  = vg * 32 + lane;
        uint4 w = *(const uint4*)&yrow[v][kc * 8];
        y2[4 * kc + 0][v] = w.x;
        y2[4 * kc + 1][v] = w.y;
        y2[4 * kc + 2][v] = w.z;
        y2[4 * kc + 3][v] = w.w;
    }
    __syncthreads();

    const int is0 = 32 * wy + 4 * r;          // i offset in tile (0..63)
    const int js0 = 16 * wx + 4 * c;          // j offset in tile (0..63)
    const __half2 z = __float2half2_rn(0.0f);
    __half2 acc0[16], acc1[16];
#pragma unroll
    for (int pp = 0; pp < 16; pp++) { acc0[pp] = z; acc1[pp] = z; }

    // ---- main loop: two 16-k banks (precision), unroll 4 ----
#pragma unroll 1
    for (int bank = 0; bank < 2; bank++) {
        __half2* acc = bank ? acc1 : acc0;
#pragma unroll 4
        for (int k8 = 0; k8 < 16; k8++) {
            const int k = bank * 16 + k8;
            uint4 iw = *(const uint4*)&y2[k][is0];
            uint4 jw = *(const uint4*)&y2[k][BLK + js0];
            __half2 ifr[4] = {*(__half2*)&iw.x, *(__half2*)&iw.y,
                              *(__half2*)&iw.z, *(__half2*)&iw.w};
            __half2 jfr[4] = {*(__half2*)&jw.x, *(__half2*)&jw.y,
                              *(__half2*)&jw.z, *(__half2*)&jw.w};
            __half2 ak = sa2[k];
#pragma unroll
            for (int ii = 0; ii < 4; ii++)
#pragma unroll
                for (int jj = 0; jj < 4; jj++) {
                    __half2 d = __habs2(__hsub2(ifr[ii], jfr[jj]));
                    acc[ii * 4 + jj] = __hfma2(d, ak, acc[ii * 4 + jj]);
                }
        }
    }

    // ---- epilogue: tmpS = exp(relu(score)), 16 independent chains ----
    float t[16];
#pragma unroll
    for (int pp = 0; pp < 16; pp++) {
        float2 f = __half22float2(acc0[pp]);
        float2 g = __half22float2(acc1[pp]);
        float s  = (f.x + f.y) + (g.x + g.y);
        t[pp] = __expf(fmaxf(s, 0.0f));
    }

    // ---- column sums over tile-i (for q-block columns) ----
    float cs[4];
#pragma unroll
    for (int jj = 0; jj < 4; jj++)
        cs[jj] = (t[0 * 4 + jj] + t[1 * 4 + jj]) + (t[2 * 4 + jj] + t[3 * 4 + jj]);
#pragma unroll
    for (int m = 4; m <= 16; m <<= 1)
#pragma unroll
        for (int jj = 0; jj < 4; jj++)
            cs[jj] += __shfl_xor_sync(0xFFFFFFFFu, cs[jj], m);
    if (r == 0)
#pragma unroll
        for (int jj = 0; jj < 4; jj++)
            cpart[wy][16 * wx + 4 * c + jj] = cs[jj];

    // ---- row sums over tile-j (== column sums for p-block columns) ----
    float rs[4];
#pragma unroll
    for (int ii = 0; ii < 4; ii++)
        rs[ii] = (t[ii * 4 + 0] + t[ii * 4 + 1]) + (t[ii * 4 + 2] + t[ii * 4 + 3]);
#pragma unroll
    for (int m = 1; m <= 2; m <<= 1)
#pragma unroll
        for (int ii = 0; ii < 4; ii++)
            rs[ii] += __shfl_xor_sync(0xFFFFFFFFu, rs[ii], m);
    if (c == 0)
#pragma unroll
        for (int ii = 0; ii < 4; ii++)
            rpart[wx][32 * wy + 4 * r + ii] = rs[ii];
    __syncthreads();

    if (tid < BLK) {
        // sum over i in p-block for columns 64q+tid
        g_colpartial[n][p][BLK * q + tid] = cpart[0][tid] + cpart[1][tid];
        if (p != q)  // diag guard: avoid ULP-differing double write
            g_colpartial[n][q][BLK * p + tid] =
                (rpart[0][tid] + rpart[1][tid]) + (rpart[2][tid] + rpart[3][tid]);
    }

    // ---- store tile and its transpose (unnormalized tmpS) ----
    float* on = out + (size_t)n * V * V;
    const int gi0 = BLK * p + is0;
    const int gj0 = BLK * q + js0;
#pragma unroll
    for (int ii = 0; ii < 4; ii++) {
        float4 o = make_float4(t[ii * 4 + 0], t[ii * 4 + 1],
                               t[ii * 4 + 2], t[ii * 4 + 3]);
        *(float4*)(on + (size_t)(gi0 + ii) * V + gj0) = o;
    }
#pragma unroll
    for (int jj = 0; jj < 4; jj++) {
        // transposed: row gj0+jj, cols gi0..gi0+3 (exact bitwise-symmetric values)
        float4 o = make_float4(t[0 * 4 + jj], t[1 * 4 + jj],
                               t[2 * 4 + jj], t[3 * 4 + jj]);
        *(float4*)(on + (size_t)(gj0 + jj) * V + gi0) = o;
    }
}

// ---------------- Kernel 2: softmax normalization over axis=1 ----------------
__global__ __launch_bounds__(256)
void norm_kernel(float* __restrict__ out) {
    __shared__ float sinv[V];
    const int n  = blockIdx.y;
    const int bx = blockIdx.x;   // 32-row chunk
    const int tid = threadIdx.x;

    for (int j = tid; j < V; j += 256) {
        float s = 0.0f;
#pragma unroll
        for (int b = 0; b < NBLK; b++) s += g_colpartial[n][b][j];
        sinv[j] = 1.0f / s;
    }
    __syncthreads();

    float* on = out + (size_t)n * V * V + (size_t)bx * 32 * V;
    for (int ii = 0; ii < 32; ii++) {
        float* row = on + (size_t)ii * V;
        row[tid]       *= sinv[tid];
        row[tid + 256] *= sinv[tid + 256];
    }
}

extern "C" void kernel_launch(void* const* d_in, const int* in_sizes, int n_in,
                              void* d_out, int out_size) {
    const float* x = (const float*)d_in[0];
    const float* a = (const float*)d_in[1];
    if (n_in >= 2 && in_sizes[0] == F && in_sizes[1] == NB * TT * V * F) {
        const float* t = x; x = a; a = t;
    }
    float* out = (float*)d_out;

    dim3 g1(NPAIR, NB);
    tile_kernel<<<g1, TPB>>>(x, a, out);
    dim3 g2(V / 32, NB);
    norm_kernel<<<g2, 256>>>(out);
}

// round 11
// speedup vs baseline: 1.3299x; 1.0278x over previous
#include <cuda_runtime.h>
#include <cuda_fp16.h>
#include <stdint.h>

#define NB 8      // batch
#define TT 8      // time (slice t = TT/2)
#define V  512    // nodes
#define F  64     // features
#define KP 32     // feature pairs
#define BLK 64    // tile edge
#define NBLK 8    // V/BLK
#define NPAIR 36  // NBLK*(NBLK+1)/2
#define TPB 256   // 8 warps: 2x4 warp grid, warp tile 32i x 16j, thread 4x4

// colpartial[n][row-block b][column j] = sum_{i in block b} tmpS[i][j].
// Each entry written by exactly one CTA (pair (min,max)) -> no atomics.
__device__ float g_colpartial[NB][NBLK][V];

// ---------------- Kernel 1: symmetric tile compute (unchanged from R9) ----------------
__global__ __launch_bounds__(TPB)
void tile_kernel(const float* __restrict__ x,
                 const float* __restrict__ a,
                 float* __restrict__ out) {
    __shared__ __half    yrow[2 * BLK][72];   // staging, row-major (144B rows)
    __shared__ uint32_t  y2[KP][2 * BLK];     // feature-major half2
    __shared__ float     cpart[2][BLK];
    __shared__ float     rpart[4][BLK];
    __shared__ __half2   sa2[KP];

    const int n   = blockIdx.y;
    int p = 0, rem = blockIdx.x;              // decode pair (p <= q)
    while (rem > (NBLK - 1) - p) { rem -= NBLK - p; p++; }
    const int q = p + rem;

    const int tid  = threadIdx.x;
    const int lane = tid & 31, wid = tid >> 5;
    const int r    = lane >> 2, c = lane & 3;
    const int wy   = wid >> 2,  wx = wid & 3;

    // ---- load i-block and j-block as fp16 ----
    const float4* xg = (const float4*)(x + ((size_t)n * TT + TT / 2) * V * F);
    for (int it = 0; it < 8; it++) {
        int idx = it * TPB + tid;
        int v = idx >> 4, ch = idx & 15;
        int src = (v < BLK) ? (BLK * p + v) : (BLK * q + (v - BLK));
        float4 w = xg[(size_t)src * 16 + ch];
        *(__half2*)&yrow[v][ch * 4]     = __float22half2_rn(make_float2(w.x, w.y));
        *(__half2*)&yrow[v][ch * 4 + 2] = __float22half2_rn(make_float2(w.z, w.w));
    }
    if (tid < KP) sa2[tid] = __float22half2_rn(make_float2(a[2 * tid], a[2 * tid + 1]));
    __syncthreads();

    // ---- transpose to feature-major ----
#pragma unroll
    for (int m = 0; m < 4; m++) {
        int u  = wid * 4 + m;
        int kc = u >> 2, vg = u & 3;
        int v  = vg * 32 + lane;
        uint4 w = *(const uint4*)&yrow[v][kc * 8];
        y2[4 * kc + 0][v] = w.x;
        y2[4 * kc + 1][v] = w.y;
        y2[4 * kc + 2][v] = w.z;
        y2[4 * kc + 3][v] = w.w;
    }
    __syncthreads();

    const int is0 = 32 * wy + 4 * r;
    const int js0 = 16 * wx + 4 * c;
    const __half2 z = __float2half2_rn(0.0f);
    __half2 acc0[16], acc1[16];
#pragma unroll
    for (int pp = 0; pp < 16; pp++) { acc0[pp] = z; acc1[pp] = z; }

#pragma unroll 1
    for (int bank = 0; bank < 2; bank++) {
        __half2* acc = bank ? acc1 : acc0;
#pragma unroll 4
        for (int k8 = 0; k8 < 16; k8++) {
            const int k = bank * 16 + k8;
            uint4 iw = *(const uint4*)&y2[k][is0];
            uint4 jw = *(const uint4*)&y2[k][BLK + js0];
            __half2 ifr[4] = {*(__half2*)&iw.x, *(__half2*)&iw.y,
                              *(__half2*)&iw.z, *(__half2*)&iw.w};
            __half2 jfr[4] = {*(__half2*)&jw.x, *(__half2*)&jw.y,
                              *(__half2*)&jw.z, *(__half2*)&jw.w};
            __half2 ak = sa2[k];
#pragma unroll
            for (int ii = 0; ii < 4; ii++)
#pragma unroll
                for (int jj = 0; jj < 4; jj++) {
                    __half2 d = __habs2(__hsub2(ifr[ii], jfr[jj]));
                    acc[ii * 4 + jj] = __hfma2(d, ak, acc[ii * 4 + jj]);
                }
        }
    }

    float t[16];
#pragma unroll
    for (int pp = 0; pp < 16; pp++) {
        float2 f = __half22float2(acc0[pp]);
        float2 g = __half22float2(acc1[pp]);
        float s  = (f.x + f.y) + (g.x + g.y);
        t[pp] = __expf(fmaxf(s, 0.0f));
    }

    // ---- column sums over tile-i ----
    float cs[4];
#pragma unroll
    for (int jj = 0; jj < 4; jj++)
        cs[jj] = (t[0 * 4 + jj] + t[1 * 4 + jj]) + (t[2 * 4 + jj] + t[3 * 4 + jj]);
#pragma unroll
    for (int m = 4; m <= 16; m <<= 1)
#pragma unroll
        for (int jj = 0; jj < 4; jj++)
            cs[jj] += __shfl_xor_sync(0xFFFFFFFFu, cs[jj], m);
    if (r == 0)
#pragma unroll
        for (int jj = 0; jj < 4; jj++)
            cpart[wy][16 * wx + 4 * c + jj] = cs[jj];

    // ---- row sums over tile-j ----
    float rs[4];
#pragma unroll
    for (int ii = 0; ii < 4; ii++)
        rs[ii] = (t[ii * 4 + 0] + t[ii * 4 + 1]) + (t[ii * 4 + 2] + t[ii * 4 + 3]);
#pragma unroll
    for (int m = 1; m <= 2; m <<= 1)
#pragma unroll
        for (int ii = 0; ii < 4; ii++)
            rs[ii] += __shfl_xor_sync(0xFFFFFFFFu, rs[ii], m);
    if (c == 0)
#pragma unroll
        for (int ii = 0; ii < 4; ii++)
            rpart[wx][32 * wy + 4 * r + ii] = rs[ii];
    __syncthreads();

    if (tid < BLK) {
        g_colpartial[n][p][BLK * q + tid] = cpart[0][tid] + cpart[1][tid];
        if (p != q)
            g_colpartial[n][q][BLK * p + tid] =
                (rpart[0][tid] + rpart[1][tid]) + (rpart[2][tid] + rpart[3][tid]);
    }

    // ---- store tile and its transpose (unnormalized tmpS) ----
    float* on = out + (size_t)n * V * V;
    const int gi0 = BLK * p + is0;
    const int gj0 = BLK * q + js0;
#pragma unroll
    for (int ii = 0; ii < 4; ii++) {
        float4 o = make_float4(t[ii * 4 + 0], t[ii * 4 + 1],
                               t[ii * 4 + 2], t[ii * 4 + 3]);
        *(float4*)(on + (size_t)(gi0 + ii) * V + gj0) = o;
    }
#pragma unroll
    for (int jj = 0; jj < 4; jj++) {
        float4 o = make_float4(t[0 * 4 + jj], t[1 * 4 + jj],
                               t[2 * 4 + jj], t[3 * 4 + jj]);
        *(float4*)(on + (size_t)(gj0 + jj) * V + gi0) = o;
    }
}

// ---------------- Kernel 2: bandwidth-oriented normalization ----------------
// Grid (64, NB) = 512 CTAs, 8 rows each. float4 RMW with MLP=4 per thread.
__global__ __launch_bounds__(256)
void norm_kernel(float* __restrict__ out) {
    __shared__ float sinv[V];
    const int n   = blockIdx.y;
    const int bx  = blockIdx.x;    // 8-row chunk (0..63)
    const int tid = threadIdx.x;

    for (int j = tid; j < V; j += 256) {
        float s = 0.0f;
#pragma unroll
        for (int b = 0; b < NBLK; b++) s += g_colpartial[n][b][j];
        sinv[j] = 1.0f / s;
    }
    __syncthreads();

    const int c4 = tid & 127;      // float4 column (0..127)
    const int r0 = tid >> 7;       // row parity (0..1)
    const float4 inv4 = ((const float4*)sinv)[c4];

    float4* on = (float4*)(out + (size_t)n * V * V + (size_t)bx * 8 * V);
    float4 v[4];
#pragma unroll
    for (int it = 0; it < 4; it++)
        v[it] = on[(size_t)(r0 + 2 * it) * 128 + c4];   // 4 independent LDG.128
#pragma unroll
    for (int it = 0; it < 4; it++) {
        v[it].x *= inv4.x; v[it].y *= inv4.y;
        v[it].z *= inv4.z; v[it].w *= inv4.w;
        on[(size_t)(r0 + 2 * it) * 128 + c4] = v[it];
    }
}

extern "C" void kernel_launch(void* const* d_in, const int* in_sizes, int n_in,
                              void* d_out, int out_size) {
    const float* x = (const float*)d_in[0];
    const float* a = (const float*)d_in[1];
    if (n_in >= 2 && in_sizes[0] == F && in_sizes[1] == NB * TT * V * F) {
        const float* t = x; x = a; a = t;
    }
    float* out = (float*)d_out;

    dim3 g1(NPAIR, NB);
    tile_kernel<<<g1, TPB>>>(x, a, out);
    dim3 g2(64, NB);
    norm_kernel<<<g2, 256>>>(out);
}